// round 1
// baseline (speedup 1.0000x reference)
#include <cuda_runtime.h>

// Problem constants: B=256 windows, N=196 tokens, C=768, H=12 heads, hd=64.
#define BATCH 256
#define NTOK  196
#define CDIM  768
#define NHEAD 12
#define HD    64
#define MROWS (BATCH * NTOK)        // 50176
#define C3    (3 * CDIM)            // 2304
#define FULLM 0xffffffffu

// Scratch (static device globals — no runtime allocation).
static __device__ float g_qkv[(size_t)MROWS * C3];     // 462 MB
static __device__ float g_attn[(size_t)MROWS * CDIM];  // 154 MB
static __device__ float g_rpb[NHEAD * NTOK * NTOK];    // 1.8 MB

// ---------------- packed f32x2 helpers (full-rate fp32 FMA on sm_10x) ----------------
__device__ __forceinline__ unsigned long long pack2(float a, float b) {
    unsigned long long r;
    asm("mov.b64 %0, {%1, %2};" : "=l"(r)
        : "r"(__float_as_uint(a)), "r"(__float_as_uint(b)));
    return r;
}
__device__ __forceinline__ void unpack2(unsigned long long v, float& a, float& b) {
    unsigned int lo, hi;
    asm("mov.b64 {%0, %1}, %2;" : "=r"(lo), "=r"(hi) : "l"(v));
    a = __uint_as_float(lo); b = __uint_as_float(hi);
}
__device__ __forceinline__ void fma2(unsigned long long& d,
                                     unsigned long long a, unsigned long long b) {
    asm("fma.rn.f32x2 %0, %1, %2, %0;" : "+l"(d) : "l"(a), "l"(b));
}

union F4U2 { float4 f; unsigned long long u[2]; };

// ---------------- RPB expansion: rpb[h][n][m] = table[rel_index[n][m]][h] ----------------
__global__ void rpb_expand_kernel(const float* __restrict__ table,
                                  const int* __restrict__ rel,
                                  float* __restrict__ rpb) {
    int i = blockIdx.x * 256 + threadIdx.x;       // over NTOK*NTOK
    if (i >= NTOK * NTOK) return;
    int ri = rel[i];
#pragma unroll
    for (int h = 0; h < NHEAD; ++h)
        rpb[h * (NTOK * NTOK) + i] = table[ri * NHEAD + h];
}

// ---------------- 128x128x8 SGEMM (NT: C[m,n] = sum_k A[m,k]*B[n,k] + bias) -------------
// biasMode 0: bias0[n] (length N).  biasMode 1: qkv bias (q_bias | 0 | v_bias).
__global__ void __launch_bounds__(256)
sgemm_nt_kernel(const float* __restrict__ A, const float* __restrict__ B,
                float* __restrict__ C, int N, int K,
                const float* __restrict__ bias0, const float* __restrict__ bias1,
                int biasMode) {
    __shared__ float As[8][132];
    __shared__ float Bs[8][132];
    int tid  = threadIdx.x;
    int tx   = tid & 15;            // 16 cols of threads -> 8 N-elems each
    int ty   = tid >> 4;            // 16 rows of threads -> 8 M-elems each
    int mBase = blockIdx.y << 7;
    int nBase = blockIdx.x << 7;
    int lrow = tid >> 1;            // 0..127
    int lcol = (tid & 1) << 2;      // 0 or 4

    const float* Ap = A + (size_t)(mBase + lrow) * K + lcol;
    const float* Bp = B + (size_t)(nBase + lrow) * K + lcol;

    unsigned long long acc[8][4];
#pragma unroll
    for (int i = 0; i < 8; ++i)
#pragma unroll
        for (int j = 0; j < 4; ++j) acc[i][j] = 0ull;

    for (int k0 = 0; k0 < K; k0 += 8) {
        float4 av = *(const float4*)(Ap + k0);
        float4 bv = *(const float4*)(Bp + k0);
        __syncthreads();
        As[lcol + 0][lrow] = av.x; As[lcol + 1][lrow] = av.y;
        As[lcol + 2][lrow] = av.z; As[lcol + 3][lrow] = av.w;
        Bs[lcol + 0][lrow] = bv.x; Bs[lcol + 1][lrow] = bv.y;
        Bs[lcol + 2][lrow] = bv.z; Bs[lcol + 3][lrow] = bv.w;
        __syncthreads();
#pragma unroll
        for (int k = 0; k < 8; ++k) {
            float4 a0 = *(const float4*)&As[k][ty * 8];
            float4 a1 = *(const float4*)&As[k][ty * 8 + 4];
            F4U2 b0, b1;
            b0.f = *(const float4*)&Bs[k][tx * 8];
            b1.f = *(const float4*)&Bs[k][tx * 8 + 4];
            unsigned long long bb[4] = { b0.u[0], b0.u[1], b1.u[0], b1.u[1] };
            float aa[8] = { a0.x, a0.y, a0.z, a0.w, a1.x, a1.y, a1.z, a1.w };
#pragma unroll
            for (int i = 0; i < 8; ++i) {
                unsigned long long ad = pack2(aa[i], aa[i]);
#pragma unroll
                for (int j = 0; j < 4; ++j) fma2(acc[i][j], ad, bb[j]);
            }
        }
    }

    float bvals[8];
#pragma unroll
    for (int j = 0; j < 8; ++j) {
        int col = nBase + tx * 8 + j;
        float bv;
        if (biasMode == 0) bv = bias0[col];
        else bv = (col < CDIM) ? bias0[col]
                : (col < 2 * CDIM ? 0.f : bias1[col - 2 * CDIM]);
        bvals[j] = bv;
    }
#pragma unroll
    for (int i = 0; i < 8; ++i) {
        float c[8];
#pragma unroll
        for (int j = 0; j < 4; ++j) unpack2(acc[i][j], c[2 * j], c[2 * j + 1]);
#pragma unroll
        for (int j = 0; j < 8; ++j) c[j] += bvals[j];
        float* Cp = C + (size_t)(mBase + ty * 8 + i) * N + nBase + tx * 8;
        *(float4*)(Cp)     = make_float4(c[0], c[1], c[2], c[3]);
        *(float4*)(Cp + 4) = make_float4(c[4], c[5], c[6], c[7]);
    }
}

// ---------------- Fused attention: one block per (b,h) ----------------
// K^T and V resident in smem; each warp processes 2 query rows at a time.
#define KT_STRIDE 200   // 196 keys + pad (odd stride avoids store conflicts)
#define ATTN_SMEM ((HD * KT_STRIDE + NTOK * HD) * 4)   // 101376 bytes

__global__ void __launch_bounds__(256)
attn_kernel(const float* __restrict__ qkv, const float* __restrict__ rpb,
            float* __restrict__ out) {
    extern __shared__ float sm[];
    float* kT = sm;                       // [HD][KT_STRIDE]
    float* vs = sm + HD * KT_STRIDE;      // [NTOK][HD]

    int bh = blockIdx.x;
    int b = bh / NHEAD, h = bh % NHEAD;
    const float* base = qkv + (size_t)b * NTOK * C3;
    int tid = threadIdx.x;

    for (int i = tid; i < NTOK * HD; i += 256) {
        int m = i >> 6, d = i & 63;
        kT[d * KT_STRIDE + m] = base[m * C3 + CDIM + h * HD + d];
        vs[i]                 = base[m * C3 + 2 * CDIM + h * HD + d];
    }
    __syncthreads();

    int warp = tid >> 5, lane = tid & 31;
    const float* rpbh = rpb + h * (NTOK * NTOK);
    const float scale = 0.125f;           // 64^-0.5
    int cnt = (lane < 4) ? 7 : 6;         // valid m-chunks per lane (196 = 6*32+4)

    for (int r = warp * 2; r < NTOK; r += 16) {
        int r1 = r + 1;
        const float* q0p = base + r  * C3 + h * HD;
        const float* q1p = base + r1 * C3 + h * HD;
        float q0a = q0p[lane] * scale, q0b = q0p[lane + 32] * scale;
        float q1a = q1p[lane] * scale, q1b = q1p[lane + 32] * scale;

        float s0[7], s1[7];
#pragma unroll
        for (int c = 0; c < 7; ++c) { s0[c] = 0.f; s1[c] = 0.f; }

#pragma unroll
        for (int half = 0; half < 2; ++half) {
            float qh0 = half ? q0b : q0a;
            float qh1 = half ? q1b : q1a;
            const float* kbase = kT + half * 32 * KT_STRIDE;
#pragma unroll 8
            for (int dd = 0; dd < 32; ++dd) {
                float qv0 = __shfl_sync(FULLM, qh0, dd);
                float qv1 = __shfl_sync(FULLM, qh1, dd);
                const float* kr = kbase + dd * KT_STRIDE;
#pragma unroll
                for (int c = 0; c < 7; ++c) {
                    float kv = kr[lane + 32 * c];   // c=6,lane>=4 reads pad: masked below
                    s0[c] = fmaf(qv0, kv, s0[c]);
                    s1[c] = fmaf(qv1, kv, s1[c]);
                }
            }
        }

        // + relative position bias, masked max
        const float* rp0 = rpbh + r  * NTOK;
        const float* rp1 = rpbh + r1 * NTOK;
        float mx0 = -1e30f, mx1 = -1e30f;
#pragma unroll
        for (int c = 0; c < 7; ++c) {
            if (c < cnt) {
                int m = lane + 32 * c;
                s0[c] += rp0[m]; s1[c] += rp1[m];
                mx0 = fmaxf(mx0, s0[c]); mx1 = fmaxf(mx1, s1[c]);
            }
        }
#pragma unroll
        for (int o = 16; o; o >>= 1) {
            mx0 = fmaxf(mx0, __shfl_xor_sync(FULLM, mx0, o));
            mx1 = fmaxf(mx1, __shfl_xor_sync(FULLM, mx1, o));
        }
        float p0[7], p1[7], sum0 = 0.f, sum1 = 0.f;
#pragma unroll
        for (int c = 0; c < 7; ++c) {
            if (c < cnt) {
                p0[c] = __expf(s0[c] - mx0); sum0 += p0[c];
                p1[c] = __expf(s1[c] - mx1); sum1 += p1[c];
            } else { p0[c] = 0.f; p1[c] = 0.f; }
        }
#pragma unroll
        for (int o = 16; o; o >>= 1) {
            sum0 += __shfl_xor_sync(FULLM, sum0, o);
            sum1 += __shfl_xor_sync(FULLM, sum1, o);
        }
        float inv0 = 1.f / sum0, inv1 = 1.f / sum1;
#pragma unroll
        for (int c = 0; c < 7; ++c) { p0[c] *= inv0; p1[c] *= inv1; }

        // PV: o[d] = sum_m p[m] * v[m][d]; d = lane, lane+32
        float o00 = 0.f, o01 = 0.f, o10 = 0.f, o11 = 0.f;
#pragma unroll
        for (int c = 0; c < 6; ++c) {
#pragma unroll 8
            for (int src = 0; src < 32; ++src) {
                float pv0 = __shfl_sync(FULLM, p0[c], src);
                float pv1 = __shfl_sync(FULLM, p1[c], src);
                const float* vr = vs + (c * 32 + src) * HD;
                float v0 = vr[lane], v1 = vr[lane + 32];
                o00 = fmaf(pv0, v0, o00); o01 = fmaf(pv0, v1, o01);
                o10 = fmaf(pv1, v0, o10); o11 = fmaf(pv1, v1, o11);
            }
        }
#pragma unroll
        for (int src = 0; src < 4; ++src) {   // tail chunk c=6 -> m=192..195
            float pv0 = __shfl_sync(FULLM, p0[6], src);
            float pv1 = __shfl_sync(FULLM, p1[6], src);
            const float* vr = vs + (192 + src) * HD;
            float v0 = vr[lane], v1 = vr[lane + 32];
            o00 = fmaf(pv0, v0, o00); o01 = fmaf(pv0, v1, o01);
            o10 = fmaf(pv1, v0, o10); o11 = fmaf(pv1, v1, o11);
        }

        float* o0p = out + (size_t)(b * NTOK + r)  * CDIM + h * HD;
        float* o1p = out + (size_t)(b * NTOK + r1) * CDIM + h * HD;
        o0p[lane] = o00; o0p[lane + 32] = o01;
        o1p[lane] = o10; o1p[lane + 32] = o11;
    }
}

// ---------------- launch ----------------
extern "C" void kernel_launch(void* const* d_in, const int* in_sizes, int n_in,
                              void* d_out, int out_size) {
    const float* x         = (const float*)d_in[0];
    const float* qkv_w     = (const float*)d_in[1];
    const float* q_bias    = (const float*)d_in[2];
    const float* v_bias    = (const float*)d_in[3];
    const float* rpb_table = (const float*)d_in[4];
    const float* proj_w    = (const float*)d_in[5];
    const float* proj_b    = (const float*)d_in[6];
    const int*   rel_index = (const int*)d_in[7];
    float* out = (float*)d_out;

    void *p_qkv, *p_attn, *p_rpb;
    cudaGetSymbolAddress(&p_qkv,  g_qkv);
    cudaGetSymbolAddress(&p_attn, g_attn);
    cudaGetSymbolAddress(&p_rpb,  g_rpb);
    float* qkv  = (float*)p_qkv;
    float* attn = (float*)p_attn;
    float* rpb  = (float*)p_rpb;

    cudaFuncSetAttribute(attn_kernel,
                         cudaFuncAttributeMaxDynamicSharedMemorySize, ATTN_SMEM);

    // 1) expand relative position bias to [H][N][N]
    rpb_expand_kernel<<<(NTOK * NTOK + 255) / 256, 256>>>(rpb_table, rel_index, rpb);

    // 2) QKV GEMM: [50176,768] @ [2304,768]^T -> [50176,2304] (+ q/v bias)
    sgemm_nt_kernel<<<dim3(C3 / 128, MROWS / 128), 256>>>(
        x, qkv_w, qkv, C3, CDIM, q_bias, v_bias, 1);

    // 3) fused window attention per (b,h)
    attn_kernel<<<BATCH * NHEAD, 256, ATTN_SMEM>>>(qkv, rpb, attn);

    // 4) output projection: [50176,768] @ [768,768]^T + proj_b
    sgemm_nt_kernel<<<dim3(CDIM / 128, MROWS / 128), 256>>>(
        attn, proj_w, out, CDIM, CDIM, proj_b, nullptr, 0);
}

// round 4
// speedup vs baseline: 2.2560x; 2.2560x over previous
#include <cuda_runtime.h>
#include <cstdint>

// Problem constants: B=256 windows, N=196 tokens, C=768, H=12 heads, hd=64.
#define BATCH 256
#define NTOK  196
#define CDIM  768
#define NHEAD 12
#define HD    64
#define MROWS (BATCH * NTOK)        // 50176
#define C3    (3 * CDIM)            // 2304
#define FULLM 0xffffffffu

// Scratch (static device globals — no runtime allocation).
static __device__ float g_qkv[(size_t)MROWS * C3];     // 462 MB
static __device__ float g_attn[(size_t)MROWS * CDIM];  // 154 MB
static __device__ float g_xr[(size_t)MROWS * CDIM];    // 154 MB (tf32-rounded x)
static __device__ float g_wqkv[(size_t)C3 * CDIM];     // 7.1 MB (tf32-rounded qkv_w)
static __device__ float g_wproj[(size_t)CDIM * CDIM];  // 2.4 MB (tf32-rounded proj_w)
static __device__ float g_rpb[NHEAD * NTOK * NTOK];    // 1.8 MB

// ---------------- packed f32x2 helpers (compile-proven on sm_100) ----------------
__device__ __forceinline__ unsigned long long pack2(float a, float b) {
    unsigned long long r;
    asm("mov.b64 %0, {%1, %2};" : "=l"(r)
        : "r"(__float_as_uint(a)), "r"(__float_as_uint(b)));
    return r;
}
__device__ __forceinline__ void unpack2(unsigned long long v, float& a, float& b) {
    unsigned int lo, hi;
    asm("mov.b64 {%0, %1}, %2;" : "=r"(lo), "=r"(hi) : "l"(v));
    a = __uint_as_float(lo); b = __uint_as_float(hi);
}
__device__ __forceinline__ void fma2(unsigned long long& d,
                                     unsigned long long a, unsigned long long b) {
    asm("fma.rn.f32x2 %0, %1, %2, %0;" : "+l"(d) : "l"(a), "l"(b));
}

__device__ __forceinline__ float tf32_rn(float x) {
    uint32_t r;
    asm("cvt.rn.tf32.f32 %0, %1;" : "=r"(r) : "f"(x));
    return __uint_as_float(r);
}
__device__ __forceinline__ uint32_t smem_u32(const void* p) {
    uint32_t a;
    asm("{ .reg .u64 t; cvta.to.shared.u64 t, %1; cvt.u32.u64 %0, t; }"
        : "=r"(a) : "l"(p));
    return a;
}
__device__ __forceinline__ void cp_async16(uint32_t saddr, const void* gaddr) {
    asm volatile("cp.async.cg.shared.global [%0], [%1], 16;"
                 :: "r"(saddr), "l"(gaddr) : "memory");
}
__device__ __forceinline__ void cp_commit() {
    asm volatile("cp.async.commit_group;" ::: "memory");
}
__device__ __forceinline__ void cp_wait0() {
    asm volatile("cp.async.wait_group 0;" ::: "memory");
}
__device__ __forceinline__ void cp_wait1() {
    asm volatile("cp.async.wait_group 1;" ::: "memory");
}
// m16n8k8 tf32 MMA (sm_80+ legacy tensor path; valid on sm_100 base)
__device__ __forceinline__ void mma_tf32(float* c, const uint32_t* a, const uint32_t* b) {
    asm volatile(
        "mma.sync.aligned.m16n8k8.row.col.f32.tf32.tf32.f32 "
        "{%0,%1,%2,%3}, {%4,%5,%6,%7}, {%8,%9}, {%0,%1,%2,%3};"
        : "+f"(c[0]), "+f"(c[1]), "+f"(c[2]), "+f"(c[3])
        : "r"(a[0]), "r"(a[1]), "r"(a[2]), "r"(a[3]), "r"(b[0]), "r"(b[1]));
}

// ---------------- elementwise tf32 rounding pass ----------------
__global__ void round_tf32_kernel(const float* __restrict__ in,
                                  float* __restrict__ out, int n4) {
    int i = blockIdx.x * 256 + threadIdx.x;
    if (i >= n4) return;
    float4 v = ((const float4*)in)[i];
    v.x = tf32_rn(v.x); v.y = tf32_rn(v.y);
    v.z = tf32_rn(v.z); v.w = tf32_rn(v.w);
    ((float4*)out)[i] = v;
}

// ---------------- RPB expansion ----------------
__global__ void rpb_expand_kernel(const float* __restrict__ table,
                                  const int* __restrict__ rel,
                                  float* __restrict__ rpb) {
    int i = blockIdx.x * 256 + threadIdx.x;
    if (i >= NTOK * NTOK) return;
    int ri = rel[i];
#pragma unroll
    for (int h = 0; h < NHEAD; ++h)
        rpb[h * (NTOK * NTOK) + i] = table[ri * NHEAD + h];
}

// ---------------- tf32 mma.sync GEMM: C[m,n] = A[m,:].B[n,:] + bias ----------------
// CTA tile 128x128, K chunk 16, double-buffered cp.async.
// 8 warps in 2(m) x 4(n); each warp 64x32 = 4x4 m16n8 tiles.
#define KCH 16
#define LDP 20                        // padded floats per smem row (conflict-free)
#define BUF_FLOATS (128 * LDP)        // 2560 floats = 10 KB

__global__ void __launch_bounds__(256)
mma_gemm_kernel(const float* __restrict__ A, const float* __restrict__ Bm,
                float* __restrict__ C, int N, int K,
                const float* __restrict__ bias0, const float* __restrict__ bias1,
                int biasMode) {
    __shared__ __align__(16) float As[2][BUF_FLOATS];
    __shared__ __align__(16) float Bs[2][BUF_FLOATS];

    int tid = threadIdx.x, wid = tid >> 5, lane = tid & 31;
    int warpM = wid >> 2, warpN = wid & 3;
    int g = lane >> 2, tg = lane & 3;
    int mBase = blockIdx.y << 7, nBase = blockIdx.x << 7;

    int lrow = tid >> 2, lc = (tid & 3) << 2;   // loader: row 0..63(+64), col 0|4|8|12
    const float* Ag = A + (size_t)(mBase + lrow) * K + lc;
    const float* Bg = Bm + (size_t)(nBase + lrow) * K + lc;
    uint32_t sA0 = smem_u32(&As[0][0]) + (lrow * LDP + lc) * 4;
    uint32_t sB0 = smem_u32(&Bs[0][0]) + (lrow * LDP + lc) * 4;
    const uint32_t rowHalf = 64 * LDP * 4;      // smem bytes for 64 rows
    const uint32_t bufStep = BUF_FLOATS * 4;

    float acc[4][4][4];
#pragma unroll
    for (int mt = 0; mt < 4; ++mt)
#pragma unroll
        for (int nt = 0; nt < 4; ++nt)
#pragma unroll
            for (int e = 0; e < 4; ++e) acc[mt][nt][e] = 0.f;

    const int chunks = K / KCH;

    // prologue: chunk 0 -> buf 0
    {
        cp_async16(sA0,           Ag);
        cp_async16(sA0 + rowHalf, Ag + (size_t)64 * K);
        cp_async16(sB0,           Bg);
        cp_async16(sB0 + rowHalf, Bg + (size_t)64 * K);
        cp_commit();
    }

    for (int i = 0; i < chunks; ++i) {
        int buf = i & 1;
        if (i + 1 < chunks) {
            int nb = (i + 1) & 1;
            int k0 = (i + 1) * KCH;
            cp_async16(sA0 + nb * bufStep,           Ag + k0);
            cp_async16(sA0 + nb * bufStep + rowHalf, Ag + (size_t)64 * K + k0);
            cp_async16(sB0 + nb * bufStep,           Bg + k0);
            cp_async16(sB0 + nb * bufStep + rowHalf, Bg + (size_t)64 * K + k0);
            cp_commit();
            cp_wait1();
        } else {
            cp_wait0();
        }
        __syncthreads();

        const float* aw = &As[buf][0] + (warpM * 64 + g) * LDP;
        const float* bw = &Bs[buf][0] + (warpN * 32 + g) * LDP;
#pragma unroll
        for (int kk = 0; kk < 2; ++kk) {
            int kb = kk * 8 + tg;
            uint32_t af[4][4], bf[4][2];
#pragma unroll
            for (int mt = 0; mt < 4; ++mt) {
                af[mt][0] = __float_as_uint(aw[(mt * 16)     * LDP + kb]);
                af[mt][1] = __float_as_uint(aw[(mt * 16 + 8) * LDP + kb]);
                af[mt][2] = __float_as_uint(aw[(mt * 16)     * LDP + kb + 4]);
                af[mt][3] = __float_as_uint(aw[(mt * 16 + 8) * LDP + kb + 4]);
            }
#pragma unroll
            for (int nt = 0; nt < 4; ++nt) {
                bf[nt][0] = __float_as_uint(bw[(nt * 8) * LDP + kb]);
                bf[nt][1] = __float_as_uint(bw[(nt * 8) * LDP + kb + 4]);
            }
#pragma unroll
            for (int mt = 0; mt < 4; ++mt)
#pragma unroll
                for (int nt = 0; nt < 4; ++nt)
                    mma_tf32(acc[mt][nt], af[mt], bf[nt]);
        }
        __syncthreads();
    }

    // epilogue
#pragma unroll
    for (int mt = 0; mt < 4; ++mt) {
        int r0 = mBase + warpM * 64 + mt * 16 + g;
#pragma unroll
        for (int nt = 0; nt < 4; ++nt) {
            int col = nBase + warpN * 32 + nt * 8 + tg * 2;
            float b0, b1;
            if (biasMode == 0) { b0 = bias0[col]; b1 = bias0[col + 1]; }
            else {
                b0 = (col < CDIM) ? bias0[col]
                   : (col < 2 * CDIM ? 0.f : bias1[col - 2 * CDIM]);
                int c1 = col + 1;
                b1 = (c1 < CDIM) ? bias0[c1]
                   : (c1 < 2 * CDIM ? 0.f : bias1[c1 - 2 * CDIM]);
            }
            float2 v0 = make_float2(acc[mt][nt][0] + b0, acc[mt][nt][1] + b1);
            float2 v1 = make_float2(acc[mt][nt][2] + b0, acc[mt][nt][3] + b1);
            *(float2*)(C + (size_t)r0 * N + col)       = v0;
            *(float2*)(C + (size_t)(r0 + 8) * N + col) = v1;
        }
    }
}

// ---------------- Fused attention: one block per (b,h), 4 rows per warp ----------------
#define KT_STRIDE 200
#define ATTN_SMEM ((HD * KT_STRIDE + NTOK * HD) * 4)   // 101376 bytes

__global__ void __launch_bounds__(256)
attn_kernel(const float* __restrict__ qkv, const float* __restrict__ rpb,
            float* __restrict__ out) {
    extern __shared__ float smf[];
    float* kT = smf;                       // [HD][KT_STRIDE]
    float* vs = smf + HD * KT_STRIDE;      // [NTOK][HD]

    int bh = blockIdx.x;
    int b = bh / NHEAD, h = bh % NHEAD;
    const float* base = qkv + (size_t)b * NTOK * C3;
    int tid = threadIdx.x;

    for (int i = tid; i < NTOK * HD; i += 256) {
        int m = i >> 6, d = i & 63;
        kT[d * KT_STRIDE + m] = base[m * C3 + CDIM + h * HD + d];
        vs[i]                 = base[m * C3 + 2 * CDIM + h * HD + d];
    }
    __syncthreads();

    int warp = tid >> 5, lane = tid & 31;
    const float* rpbh = rpb + h * (NTOK * NTOK);
    const float scale = 0.125f;
    int cnt = (lane < 4) ? 7 : 6;          // valid m-chunks per lane (196 = 6*32+4)

    for (int r = warp * 4; r < NTOK; r += 32) {
        float qa[4], qb[4];
#pragma unroll
        for (int rr = 0; rr < 4; ++rr) {
            const float* qp = base + (r + rr) * C3 + h * HD;
            qa[rr] = qp[lane] * scale;
            qb[rr] = qp[lane + 32] * scale;
        }

        unsigned long long acc01[7], acc23[7];
#pragma unroll
        for (int c = 0; c < 7; ++c) { acc01[c] = 0ull; acc23[c] = 0ull; }

#pragma unroll
        for (int half = 0; half < 2; ++half) {
            float h0 = half ? qb[0] : qa[0];
            float h1 = half ? qb[1] : qa[1];
            float h2 = half ? qb[2] : qa[2];
            float h3 = half ? qb[3] : qa[3];
            const float* kbase = kT + half * 32 * KT_STRIDE;
#pragma unroll 4
            for (int dd = 0; dd < 32; ++dd) {
                float v0 = __shfl_sync(FULLM, h0, dd);
                float v1 = __shfl_sync(FULLM, h1, dd);
                float v2 = __shfl_sync(FULLM, h2, dd);
                float v3 = __shfl_sync(FULLM, h3, dd);
                unsigned long long qp01 = pack2(v0, v1);
                unsigned long long qp23 = pack2(v2, v3);
                const float* kr = kbase + dd * KT_STRIDE;
#pragma unroll
                for (int c = 0; c < 7; ++c) {
                    float kv = kr[lane + 32 * c];   // c=6 tail garbage masked below
                    unsigned long long kp = pack2(kv, kv);
                    fma2(acc01[c], qp01, kp);
                    fma2(acc23[c], qp23, kp);
                }
            }
        }

        float s[4][7];
#pragma unroll
        for (int c = 0; c < 7; ++c) {
            unpack2(acc01[c], s[0][c], s[1][c]);
            unpack2(acc23[c], s[2][c], s[3][c]);
        }

        float p[4][7], inv[4];
#pragma unroll
        for (int rr = 0; rr < 4; ++rr) {
            const float* rp = rpbh + (r + rr) * NTOK;
            float mx = -1e30f;
#pragma unroll
            for (int c = 0; c < 7; ++c) {
                if (c < cnt) {
                    s[rr][c] += rp[lane + 32 * c];
                    mx = fmaxf(mx, s[rr][c]);
                }
            }
#pragma unroll
            for (int o = 16; o; o >>= 1)
                mx = fmaxf(mx, __shfl_xor_sync(FULLM, mx, o));
            float sum = 0.f;
#pragma unroll
            for (int c = 0; c < 7; ++c) {
                if (c < cnt) { p[rr][c] = __expf(s[rr][c] - mx); sum += p[rr][c]; }
                else p[rr][c] = 0.f;
            }
#pragma unroll
            for (int o = 16; o; o >>= 1)
                sum += __shfl_xor_sync(FULLM, sum, o);
            inv[rr] = 1.f / sum;
        }
#pragma unroll
        for (int rr = 0; rr < 4; ++rr)
#pragma unroll
            for (int c = 0; c < 7; ++c) p[rr][c] *= inv[rr];

        // PV
        unsigned long long a0_01 = 0ull, a0_23 = 0ull, a1_01 = 0ull, a1_23 = 0ull;
#pragma unroll
        for (int c = 0; c < 7; ++c) {
            int lim = (c == 6) ? 4 : 32;
#pragma unroll 4
            for (int src = 0; src < lim; ++src) {
                float p0 = __shfl_sync(FULLM, p[0][c], src);
                float p1 = __shfl_sync(FULLM, p[1][c], src);
                float p2 = __shfl_sync(FULLM, p[2][c], src);
                float p3 = __shfl_sync(FULLM, p[3][c], src);
                unsigned long long pp01 = pack2(p0, p1);
                unsigned long long pp23 = pack2(p2, p3);
                const float* vr = vs + (c * 32 + src) * HD;
                float v0 = vr[lane], v1 = vr[lane + 32];
                unsigned long long v0p = pack2(v0, v0);
                unsigned long long v1p = pack2(v1, v1);
                fma2(a0_01, pp01, v0p); fma2(a0_23, pp23, v0p);
                fma2(a1_01, pp01, v1p); fma2(a1_23, pp23, v1p);
            }
        }
        float o00, o01, o10, o11, o20, o21, o30, o31;
        unpack2(a0_01, o00, o10); unpack2(a0_23, o20, o30);
        unpack2(a1_01, o01, o11); unpack2(a1_23, o21, o31);

        // store tf32-rounded (next GEMM consumes via raw cp.async)
        float* op = out + (size_t)(b * NTOK + r) * CDIM + h * HD;
        op[lane] = tf32_rn(o00);              op[lane + 32] = tf32_rn(o01);
        op += CDIM; op[lane] = tf32_rn(o10);  op[lane + 32] = tf32_rn(o11);
        op += CDIM; op[lane] = tf32_rn(o20);  op[lane + 32] = tf32_rn(o21);
        op += CDIM; op[lane] = tf32_rn(o30);  op[lane + 32] = tf32_rn(o31);
    }
}

// ---------------- launch ----------------
extern "C" void kernel_launch(void* const* d_in, const int* in_sizes, int n_in,
                              void* d_out, int out_size) {
    const float* x         = (const float*)d_in[0];
    const float* qkv_w     = (const float*)d_in[1];
    const float* q_bias    = (const float*)d_in[2];
    const float* v_bias    = (const float*)d_in[3];
    const float* rpb_table = (const float*)d_in[4];
    const float* proj_w    = (const float*)d_in[5];
    const float* proj_b    = (const float*)d_in[6];
    const int*   rel_index = (const int*)d_in[7];
    float* out = (float*)d_out;

    void *p_qkv, *p_attn, *p_xr, *p_wqkv, *p_wproj, *p_rpb;
    cudaGetSymbolAddress(&p_qkv,   g_qkv);
    cudaGetSymbolAddress(&p_attn,  g_attn);
    cudaGetSymbolAddress(&p_xr,    g_xr);
    cudaGetSymbolAddress(&p_wqkv,  g_wqkv);
    cudaGetSymbolAddress(&p_wproj, g_wproj);
    cudaGetSymbolAddress(&p_rpb,   g_rpb);
    float* qkv   = (float*)p_qkv;
    float* attn  = (float*)p_attn;
    float* xr    = (float*)p_xr;
    float* wqkv  = (float*)p_wqkv;
    float* wproj = (float*)p_wproj;
    float* rpb   = (float*)p_rpb;

    cudaFuncSetAttribute(attn_kernel,
                         cudaFuncAttributeMaxDynamicSharedMemorySize, ATTN_SMEM);

    // 0) pre-round GEMM inputs to tf32 (RN) so cp.async can copy raw bits
    {
        int n4x = MROWS * CDIM / 4;
        round_tf32_kernel<<<(n4x + 255) / 256, 256>>>(x, xr, n4x);
        int n4w = C3 * CDIM / 4;
        round_tf32_kernel<<<(n4w + 255) / 256, 256>>>(qkv_w, wqkv, n4w);
        int n4p = CDIM * CDIM / 4;
        round_tf32_kernel<<<(n4p + 255) / 256, 256>>>(proj_w, wproj, n4p);
    }

    // 1) expand relative position bias to [H][N][N]
    rpb_expand_kernel<<<(NTOK * NTOK + 255) / 256, 256>>>(rpb_table, rel_index, rpb);

    // 2) QKV GEMM: [50176,768] @ [2304,768]^T -> [50176,2304] (+ q/v bias)
    mma_gemm_kernel<<<dim3(C3 / 128, MROWS / 128), 256>>>(
        xr, wqkv, qkv, C3, CDIM, q_bias, v_bias, 1);

    // 3) fused window attention per (b,h); outputs tf32-rounded
    attn_kernel<<<BATCH * NHEAD, 256, ATTN_SMEM>>>(qkv, rpb, attn);

    // 4) output projection: [50176,768] @ [768,768]^T + proj_b
    mma_gemm_kernel<<<dim3(CDIM / 128, MROWS / 128), 256>>>(
        attn, wproj, out, CDIM, CDIM, proj_b, nullptr, 0);
}